// round 7
// baseline (speedup 1.0000x reference)
#include <cuda_runtime.h>
#include <cuda_bf16.h>

// ShiftingLayer: out[b,d,c] = (1/AMP) * sum_s exp(-(s - center[b,d])^2) * in[b,s,c]
//   center[b,d] = (d+1 + w[b,d]) * (S/D), s = 1..S (1-indexed).
//
// Per-d private window of K=8 rows around floor(center); omitted weights
// <= exp(-16) ~ 1.1e-7 relative. Each thread handles TWO channel quads of one
// d (lane, lane+32): 16 independent LDG.128 per thread amortize the serial
// wts->address->load latency chain and halve MUFU/ALU per useful FLOP.

#define B_ 16
#define S_ 4096
#define C_ 256
#define D_ 1024

constexpr int   DT      = 8;          // d's per block (32 lanes each, 2 quads/lane)
constexpr int   K_      = 8;          // window rows per d
constexpr int   RAD     = 3;          // floor(c)-RAD .. floor(c)-RAD+K-1
constexpr float SCALE   = (float)S_ / (float)D_;   // 4.0
constexpr float INV_AMP = 1.0f / 1.772637204826652f;

__global__ __launch_bounds__(256, 4)
void ShiftingLayer_53798760349850_kernel(const float* __restrict__ in,
                                         const float* __restrict__ wts,
                                         float* __restrict__ out) {
    const int tid  = threadIdx.x;
    const int b    = blockIdx.x >> 7;                 // / (D/DT = 128)
    const int d    = ((blockIdx.x & 127) << 3) + (tid >> 5);
    const int lane = tid & 31;                        // quads: lane, lane+32

    // Window start (address chain head)
    const float w = __ldg(&wts[b * D_ + d]);
    const float c = ((float)(d + 1) + w) * SCALE;
    int ss = (int)floorf(c) - RAD;                    // 1-indexed window start
    if (ss < 1) ss = 1;
    if (ss > S_ - K_ + 1) ss = S_ - K_ + 1;

    const int qstride = C_ / 4;                       // 64 quads per row
    const float4* p = reinterpret_cast<const float4*>(in)
                      + (b * S_ + (ss - 1)) * qstride + lane;

    // 16 independent LDG.128 (two quads x 8 rows)
    float4 x0[K_], x1[K_];
#pragma unroll
    for (int k = 0; k < K_; k++) {
        x0[k] = p[k * qstride];
        x1[k] = p[k * qstride + 32];
    }

    // Per-d Gaussian weights (computed once, used for both quads)
    float wk[K_];
#pragma unroll
    for (int k = 0; k < K_; k++) {
        const float diff = (float)(ss + k) - c;
        wk[k] = __expf(-diff * diff);
    }

    float4 a0 = make_float4(0.f, 0.f, 0.f, 0.f);
    float4 a1 = make_float4(0.f, 0.f, 0.f, 0.f);
#pragma unroll
    for (int k = 0; k < K_; k++) {
        a0.x = fmaf(wk[k], x0[k].x, a0.x);
        a0.y = fmaf(wk[k], x0[k].y, a0.y);
        a0.z = fmaf(wk[k], x0[k].z, a0.z);
        a0.w = fmaf(wk[k], x0[k].w, a0.w);
        a1.x = fmaf(wk[k], x1[k].x, a1.x);
        a1.y = fmaf(wk[k], x1[k].y, a1.y);
        a1.z = fmaf(wk[k], x1[k].z, a1.z);
        a1.w = fmaf(wk[k], x1[k].w, a1.w);
    }
    a0.x *= INV_AMP; a0.y *= INV_AMP; a0.z *= INV_AMP; a0.w *= INV_AMP;
    a1.x *= INV_AMP; a1.y *= INV_AMP; a1.z *= INV_AMP; a1.w *= INV_AMP;

    float4* o = reinterpret_cast<float4*>(out) + (b * D_ + d) * qstride + lane;
    o[0]  = a0;
    o[32] = a1;
}

extern "C" void kernel_launch(void* const* d_in, const int* in_sizes, int n_in,
                              void* d_out, int out_size) {
    const float* in  = (const float*)d_in[0];   // (16, 4096, 256) f32
    const float* wts = (const float*)d_in[1];   // (16, 1024) f32
    float*       out = (float*)d_out;           // (16, 1024, 256) f32

    dim3 grid(B_ * (D_ / DT));   // 2048
    dim3 block(256);
    ShiftingLayer_53798760349850_kernel<<<grid, block>>>(in, wts, out);
}

// round 8
// speedup vs baseline: 1.5627x; 1.5627x over previous
#include <cuda_runtime.h>
#include <cuda_bf16.h>

// ShiftingLayer: out[b,d,c] = (1/AMP) * sum_s exp(-(s - center[b,d])^2) * in[b,s,c]
//   center[b,d] = (d+1 + w[b,d]) * (S/D), s = 1..S (1-indexed).
//
// R4 skeleton (best known: serialized per-thread d-groups, smem weights),
// with K=6 window (omitted weights <= exp(-9) ~ 1.2e-4 rel, gate is 1e-3)
// and INV_AMP folded into the staged weights.

#define B_ 16
#define S_ 4096
#define C_ 256
#define D_ 1024

constexpr int   DT      = 16;         // d's per block
constexpr int   K_      = 6;          // window rows per d
constexpr int   RAD     = 2;          // floor(c)-RAD .. floor(c)+RAD+1
constexpr float SCALE   = (float)S_ / (float)D_;   // 4.0
constexpr float INV_AMP = 1.0f / 1.772637204826652f;

__global__ __launch_bounds__(256, 4)
void ShiftingLayer_53798760349850_kernel(const float* __restrict__ in,
                                         const float* __restrict__ wts,
                                         float* __restrict__ out) {
    __shared__ float s_w[DT][K_ + 2];   // +2 pad: keep rows bank-staggered
    __shared__ int   s_ss[DT];

    const int tid = threadIdx.x;
    const int b   = blockIdx.x / (D_ / DT);
    const int d0  = (blockIdx.x % (D_ / DT)) * DT;

    // Precompute windows + weights (INV_AMP folded in): DT*K_=96 threads.
    if (tid < DT * K_) {
        const int j = tid / K_;
        const int k = tid - j * K_;
        const float c = ((float)(d0 + j + 1) + wts[b * D_ + d0 + j]) * SCALE;
        int ss = (int)floorf(c) - RAD;            // 1-indexed window start
        if (ss < 1) ss = 1;
        if (ss > S_ - K_ + 1) ss = S_ - K_ + 1;
        const float diff = (float)(ss + k) - c;
        s_w[j][k] = __expf(-diff * diff) * INV_AMP;
        if (k == 0) s_ss[j] = ss;
    }
    __syncthreads();

    const int cq = tid & 63;            // channel quad (64 per row)
    const int g  = tid >> 6;            // d-group 0..3

    const int qstride = C_ / 4;
    const float4* inb = reinterpret_cast<const float4*>(in) + (b * S_) * qstride + cq;
    float4* outb = reinterpret_cast<float4*>(out) + (b * D_ + d0) * qstride + cq;

#pragma unroll
    for (int jj = 0; jj < 4; jj++) {
        const int j  = g * 4 + jj;
        const int ss = s_ss[j];

        const float4* p = inb + (ss - 1) * qstride;

        // Issue all 6 independent LDG.128 first
        float4 x[K_];
#pragma unroll
        for (int k = 0; k < K_; k++)
            x[k] = p[k * qstride];

        // Broadcast weight reads (overlap with load latency)
        float wk[K_];
#pragma unroll
        for (int k = 0; k < K_; k++)
            wk[k] = s_w[j][k];

        float4 acc = make_float4(0.f, 0.f, 0.f, 0.f);
#pragma unroll
        for (int k = 0; k < K_; k++) {
            acc.x = fmaf(wk[k], x[k].x, acc.x);
            acc.y = fmaf(wk[k], x[k].y, acc.y);
            acc.z = fmaf(wk[k], x[k].z, acc.z);
            acc.w = fmaf(wk[k], x[k].w, acc.w);
        }

        outb[j * qstride] = acc;
    }
}

extern "C" void kernel_launch(void* const* d_in, const int* in_sizes, int n_in,
                              void* d_out, int out_size) {
    const float* in  = (const float*)d_in[0];   // (16, 4096, 256) f32
    const float* wts = (const float*)d_in[1];   // (16, 1024) f32
    float*       out = (float*)d_out;           // (16, 1024, 256) f32

    dim3 grid(B_ * (D_ / DT));   // 1024
    dim3 block(256);
    ShiftingLayer_53798760349850_kernel<<<grid, block>>>(in, wts, out);
}